// round 15
// baseline (speedup 1.0000x reference)
#include <cuda_runtime.h>
#include <cuda_bf16.h>
#include <cstdint>

#define B_  4
#define S_  1024
#define DM_ 1024
#define H_  16
#define D_  64
#define SE_ 512
#define DF_ 512

typedef __nv_bfloat16 bf16;
typedef __nv_bfloat162 bf162;

// ===================== scratch =====================
__device__ float g_Y[B_*S_*DM_];

__device__ __align__(16) bf16 g_Q  [B_*H_*S_ *D_];
__device__ __align__(16) bf16 g_K  [B_*H_*S_ *D_];
__device__ __align__(16) bf16 g_V  [B_*H_*S_ *D_];
__device__ __align__(16) bf16 g_FK [B_*H_*SE_*D_];
__device__ __align__(16) bf16 g_FV [B_*H_*SE_*D_];
__device__ __align__(16) bf16 g_E  [2047*64];

__device__ __align__(16) bf16 g_hs  [B_*S_*DM_];
__device__ __align__(16) bf16 g_enc [B_*SE_*DF_];
__device__ __align__(16) bf16 g_ctx [B_*S_*DM_];
#define WOFF_Q  0
#define WOFF_K  1048576
#define WOFF_V  2097152
#define WOFF_O  3145728
#define WOFF_FK 4194304
#define WOFF_FV 4718592
__device__ __align__(16) bf16 g_wb[5242880];

// ===================== helpers =====================
__device__ __forceinline__ uint32_t smem_to_u32(const void* p) {
    uint32_t a;
    asm("{ .reg .u64 t; cvta.to.shared.u64 t, %1; cvt.u32.u64 %0, t; }" : "=r"(a) : "l"(p));
    return a;
}
__device__ __forceinline__ void cp_async16(uint32_t saddr, const void* gptr) {
    asm volatile("cp.async.cg.shared.global [%0], [%1], 16;" :: "r"(saddr), "l"(gptr));
}
#define CP_COMMIT() asm volatile("cp.async.commit_group;" ::: "memory")
#define CP_WAIT0()  asm volatile("cp.async.wait_group 0;" ::: "memory")
#define CP_WAIT1()  asm volatile("cp.async.wait_group 1;" ::: "memory")
#define CP_WAIT2()  asm volatile("cp.async.wait_group 2;" ::: "memory")
__device__ __forceinline__ void ldsm_x4(uint32_t& r0, uint32_t& r1, uint32_t& r2,
                                        uint32_t& r3, uint32_t addr) {
    asm volatile("ldmatrix.sync.aligned.m8n8.x4.shared.b16 {%0,%1,%2,%3}, [%4];"
                 : "=r"(r0), "=r"(r1), "=r"(r2), "=r"(r3) : "r"(addr));
}
__device__ __forceinline__ void ldsm_x4_t(uint32_t& r0, uint32_t& r1, uint32_t& r2,
                                          uint32_t& r3, uint32_t addr) {
    asm volatile("ldmatrix.sync.aligned.m8n8.x4.trans.shared.b16 {%0,%1,%2,%3}, [%4];"
                 : "=r"(r0), "=r"(r1), "=r"(r2), "=r"(r3) : "r"(addr));
}
__device__ __forceinline__ void mma16816(float* c, const uint32_t* a,
                                         uint32_t b0, uint32_t b1) {
    asm volatile(
        "mma.sync.aligned.m16n8k16.row.col.f32.bf16.bf16.f32 "
        "{%0,%1,%2,%3}, {%4,%5,%6,%7}, {%8,%9}, {%0,%1,%2,%3};"
        : "+f"(c[0]), "+f"(c[1]), "+f"(c[2]), "+f"(c[3])
        : "r"(a[0]), "r"(a[1]), "r"(a[2]), "r"(a[3]), "r"(b0), "r"(b1));
}
__device__ __forceinline__ uint32_t pack2bf(float lo, float hi) {
    bf162 v = __floats2bfloat162_rn(lo, hi);
    return *reinterpret_cast<uint32_t*>(&v);
}

// ===================== merged fp32 -> bf16 convert (4 float4 per thread) =======
__device__ __forceinline__ void cvt_one(const float* __restrict__ src, bf16* dst, int i) {
    float4 v = reinterpret_cast<const float4*>(src)[i];
    bf162* d2 = reinterpret_cast<bf162*>(dst);
    d2[2*i]   = __floats2bfloat162_rn(v.x, v.y);
    d2[2*i+1] = __floats2bfloat162_rn(v.z, v.w);
}

__global__ void __launch_bounds__(256)
k_cvt_all(const float* hs, const float* enc, const float* Wq, const float* Wk,
          const float* Wv, const float* Wo, const float* Wfk, const float* Wfv,
          const float* E) {
    int blk = blockIdx.x, tid = threadIdx.x;
    const float* src; bf16* dst; int lb, n4;
    if      (blk < 1024) { src=hs;  dst=g_hs;         lb=0;    n4=1048576; }
    else if (blk < 1280) { src=enc; dst=g_enc;        lb=1024; n4=262144; }
    else if (blk < 1536) { src=Wq;  dst=g_wb+WOFF_Q;  lb=1280; n4=262144; }
    else if (blk < 1792) { src=Wk;  dst=g_wb+WOFF_K;  lb=1536; n4=262144; }
    else if (blk < 2048) { src=Wv;  dst=g_wb+WOFF_V;  lb=1792; n4=262144; }
    else if (blk < 2304) { src=Wo;  dst=g_wb+WOFF_O;  lb=2048; n4=262144; }
    else if (blk < 2432) { src=Wfk; dst=g_wb+WOFF_FK; lb=2304; n4=131072; }
    else if (blk < 2560) { src=Wfv; dst=g_wb+WOFF_FV; lb=2432; n4=131072; }
    else                 { src=E;   dst=g_E;          lb=2560; n4=32752; }
    int i0 = (blk - lb) * 1024 + tid;
    #pragma unroll
    for (int r = 0; r < 4; r++) {
        int i = i0 + r * 256;
        if (i < n4) cvt_one(src, dst, i);
    }
}

// ===================== mma.sync bf16 GEMM (3-stage, 1 barrier/chunk) ============
#define GSTAGE 20480
#define GEMM_SMEM_BYTES (3*GSTAGE)

__global__ void __launch_bounds__(256, 3) k_gemm(const float* __restrict__ b0p,
                                                 const float* __restrict__ b1p,
                                                 const float* __restrict__ b2p,
                                                 const float* __restrict__ b3p,
                                                 const float* __restrict__ b4p,
                                                 const float* __restrict__ res,
                                                 int base) {
    const int which = base + blockIdx.z;
    if (which == 3 || which == 4) { if (blockIdx.y >= 16) return; }

    extern __shared__ char dsm[];
    const uint32_t sbase = smem_to_u32(dsm);
    const int tid = threadIdx.x;
    const int lane = tid & 31, wid = tid >> 5;
    const int warp_m = wid & 1, warp_n = wid >> 1;
    const int m0 = blockIdx.y * 128, n0 = blockIdx.x * 128;
    const float* bias = blockIdx.z == 0 ? b0p : blockIdx.z == 1 ? b1p
                      : blockIdx.z == 2 ? b2p : blockIdx.z == 3 ? b3p : b4p;

    const bf16 *A, *W;
    bf16* dst = nullptr;
    int K, Sx;
    switch (which) {
        case 0: A=g_hs;  W=g_wb+WOFF_Q;  dst=g_Q;  K=1024; Sx=1024; break;
        case 1: A=g_hs;  W=g_wb+WOFF_K;  dst=g_K;  K=1024; Sx=1024; break;
        case 2: A=g_hs;  W=g_wb+WOFF_V;  dst=g_V;  K=1024; Sx=1024; break;
        case 3: A=g_enc; W=g_wb+WOFF_FK; dst=g_FK; K=512;  Sx=512;  break;
        case 4: A=g_enc; W=g_wb+WOFF_FV; dst=g_FV; K=512;  Sx=512;  break;
        default:A=g_ctx; W=g_wb+WOFF_O;  K=1024; Sx=1024; break;
    }
    const int nk = K >> 5;

    const int sub = lane >> 3, lr = lane & 7;
    const int a_row = (sub & 1) * 8 + lr, a_colB = (sub >> 1) * 16;
    const int b_row = (sub >> 1) * 8 + lr, b_colB = (sub & 1) * 16;

    float acc[4][4][4] = {};

    auto cp_chunk = [&](int c) {
        const int s = c % 3;
        const uint32_t st = sbase + s * GSTAGE;
        const int k0 = c * 32;
        #pragma unroll
        for (int i = 0; i < 2; i++) {
            int u = tid + i * 256;
            int r = u >> 2, cg = u & 3;
            uint32_t so = (uint32_t)(r * 80 + cg * 16);
            cp_async16(st + so,         A + (size_t)(m0 + r) * K + k0 + cg * 8);
            cp_async16(st + 10240 + so, W + (size_t)(n0 + r) * K + k0 + cg * 8);
        }
        CP_COMMIT();
    };

    cp_chunk(0); cp_chunk(1);
    for (int c = 0; c < nk; c++) {
        if (c + 1 < nk) { CP_WAIT1(); } else { CP_WAIT0(); }
        __syncthreads();          // chunk c visible; all warps done with c-1
        if (c + 2 < nk) cp_chunk(c + 2);   // overwrite stage (c-1)%3 — safe
        const uint32_t st = sbase + (c % 3) * GSTAGE;
        #pragma unroll
        for (int ks = 0; ks < 2; ks++) {
            uint32_t bh[8];
            #pragma unroll
            for (int np = 0; np < 2; np++) {
                uint32_t baddr = st + 10240 +
                    (uint32_t)((warp_n * 32 + np * 16 + b_row) * 80 + ks * 32 + b_colB);
                ldsm_x4(bh[np*4+0], bh[np*4+1], bh[np*4+2], bh[np*4+3], baddr);
            }
            #pragma unroll
            for (int mf = 0; mf < 4; mf++) {
                uint32_t ah[4];
                uint32_t aaddr = st +
                    (uint32_t)((warp_m * 64 + mf * 16 + a_row) * 80 + ks * 32 + a_colB);
                ldsm_x4(ah[0], ah[1], ah[2], ah[3], aaddr);
                #pragma unroll
                for (int nf = 0; nf < 4; nf++) {
                    const int np = nf >> 1, q = nf & 1;
                    mma16816(acc[mf][nf], ah, bh[np*4 + q*2], bh[np*4 + q*2 + 1]);
                }
            }
        }
    }

    const int gID = lane >> 2, tc2 = (lane & 3) * 2;
    #pragma unroll
    for (int mf = 0; mf < 4; mf++) {
        #pragma unroll
        for (int nf = 0; nf < 4; nf++) {
            int n = n0 + warp_n * 32 + nf * 8 + tc2;
            float bb0 = bias[n], bb1 = bias[n + 1];
            #pragma unroll
            for (int half = 0; half < 2; half++) {
                int m = m0 + warp_m * 64 + mf * 16 + gID + half * 8;
                float v0 = acc[mf][nf][half*2 + 0] + bb0;
                float v1 = acc[mf][nf][half*2 + 1] + bb1;
                if (which < 5) {
                    int bb = m / Sx, srow = m - bb * Sx;
                    int h = n >> 6, d = n & 63;
                    size_t o = (((size_t)(bb * H_ + h)) * Sx + srow) * 64 + d;
                    *reinterpret_cast<bf162*>(dst + o) = __floats2bfloat162_rn(v0, v1);
                } else {
                    const float2 r2 = *reinterpret_cast<const float2*>(
                        res + (size_t)m * DM_ + n);
                    float2 o = {v0 + r2.x, v1 + r2.y};
                    *reinterpret_cast<float2*>(g_Y + (size_t)m * DM_ + n) = o;
                }
            }
        }
    }
}

// ===================== tensor-core flash attention (bf16) =====================
// R11/R12/R14 kernel, unchanged (proven local optimum).
#define AT_K  0
#define AT_V  9216
#define AT_E  18432
#define AT_QE 36864
#define AT_KE 48128
#define AT_MK 59392
#define ATTN_SMEM_BYTES 63488

__global__ void __launch_bounds__(128, 3)
k_attn(const float* __restrict__ mask) {
    extern __shared__ char dsm[];
    const uint32_t sb = smem_to_u32(dsm);
    const int tid = threadIdx.x;
    const int lane = tid & 31, w = tid >> 5;
    const int g = lane >> 2, t = lane & 3;
    const int sub = lane >> 3, lr = lane & 7;
    const int l0 = blockIdx.x * 64;
    const int h  = blockIdx.y;
    const int b  = blockIdx.z;
    const size_t bh = (size_t)(b * H_ + h);
    const float SC2 = 0.125f * 1.44269504f;
    const float L2E = 1.44269504f;

    {
        float* mks = reinterpret_cast<float*>(dsm + AT_MK);
        for (int u = tid; u < 256; u += 128) {
            float4 m4 = reinterpret_cast<const float4*>(mask + b * S_)[u];
            m4.x *= L2E; m4.y *= L2E; m4.z *= L2E; m4.w *= L2E;
            reinterpret_cast<float4*>(mks)[u] = m4;
        }
    }
    {
        size_t qb = (bh * S_ + l0) * 64;
        for (int u = tid; u < 512; u += 128) {
            int r = u >> 3, c = u & 7;
            cp_async16(sb + AT_K + (uint32_t)(r * 144 + c * 16),
                       g_Q + qb + (size_t)r * 64 + c * 8);
        }
        CP_COMMIT(); CP_WAIT0();
    }
    __syncthreads();
    uint32_t qf[4][4];
    #pragma unroll
    for (int ks = 0; ks < 4; ks++) {
        uint32_t ad = sb + AT_K +
            (uint32_t)((16*w + (sub & 1)*8 + lr) * 144 + (sub >> 1)*16 + ks*32);
        ldsm_x4(qf[ks][0], qf[ks][1], qf[ks][2], qf[ks][3], ad);
    }

    float acc[8][4] = {};
    float save[8][4];
    float lrow[2] = {0.f, 0.f};
    const int g16 = 16 * w + g;

    for (int tt = 0; tt < 16; tt++) {
        const int r0 = tt * 64;
        __syncthreads();
        {
            const int jbase = l0 - r0 + 960;
            const bf16* Ep = g_E + (size_t)jbase * 64;
            for (int u = tid; u < 1016; u += 128) {
                int r = u >> 3, c = u & 7;
                cp_async16(sb + AT_E + (uint32_t)(r * 144 + c * 16),
                           Ep + (size_t)r * 64 + c * 8);
            }
            CP_COMMIT();
        }
        {
            size_t kb = (bh * S_ + r0) * 64;
            for (int u = tid; u < 512; u += 128) {
                int r = u >> 3, c = u & 7;
                cp_async16(sb + AT_K + (uint32_t)(r * 144 + c * 16),
                           g_K + kb + (size_t)r * 64 + c * 8);
            }
            CP_COMMIT();
        }
        {
            size_t kb = (bh * S_ + r0) * 64;
            for (int u = tid; u < 512; u += 128) {
                int r = u >> 3, c = u & 7;
                cp_async16(sb + AT_V + (uint32_t)(r * 144 + c * 16),
                           g_V + kb + (size_t)r * 64 + c * 8);
            }
            CP_COMMIT();
        }

        CP_WAIT2(); __syncthreads();

        {
            float qe[10][4] = {};
            #pragma unroll
            for (int ks = 0; ks < 4; ks++) {
                #pragma unroll
                for (int np = 0; np < 5; np++) {
                    uint32_t e0, e1, e2, e3;
                    uint32_t ad = sb + AT_E +
                        (uint32_t)((16*w + np*16 + (sub >> 1)*8 + lr) * 144
                                   + (sub & 1)*16 + ks*32);
                    ldsm_x4(e0, e1, e2, e3, ad);
                    mma16816(qe[2*np],   qf[ks], e0, e1);
                    mma16816(qe[2*np+1], qf[ks], e2, e3);
                }
            }
            #pragma unroll
            for (int nf = 0; nf < 10; nf++) {
                uint32_t c2 = (uint32_t)((nf*8 + t*2) * 2);
                *reinterpret_cast<uint32_t*>(dsm + AT_QE + g16*176 + c2)
                    = pack2bf(qe[nf][0], qe[nf][1]);
                *reinterpret_cast<uint32_t*>(dsm + AT_QE + (g16 + 8)*176 + c2)
                    = pack2bf(qe[nf][2], qe[nf][3]);
            }
        }

        CP_WAIT1(); __syncthreads();

        {
            float ke[10][4] = {};
            const int kb16 = 16 * (3 - w);
            #pragma unroll
            for (int ks = 0; ks < 4; ks++) {
                uint32_t ka[4];
                uint32_t aad = sb + AT_K +
                    (uint32_t)((16*w + (sub & 1)*8 + lr) * 144 + (sub >> 1)*16 + ks*32);
                ldsm_x4(ka[0], ka[1], ka[2], ka[3], aad);
                #pragma unroll
                for (int np = 0; np < 5; np++) {
                    uint32_t e0, e1, e2, e3;
                    uint32_t ad = sb + AT_E +
                        (uint32_t)((kb16 + np*16 + (sub >> 1)*8 + lr) * 144
                                   + (sub & 1)*16 + ks*32);
                    ldsm_x4(e0, e1, e2, e3, ad);
                    mma16816(ke[2*np],   ka, e0, e1);
                    mma16816(ke[2*np+1], ka, e2, e3);
                }
            }
            #pragma unroll
            for (int nf = 0; nf < 10; nf++) {
                uint32_t c2 = (uint32_t)((nf*8 + t*2) * 2);
                *reinterpret_cast<uint32_t*>(dsm + AT_KE + g16*176 + c2)
                    = pack2bf(ke[nf][0], ke[nf][1]);
                *reinterpret_cast<uint32_t*>(dsm + AT_KE + (g16 + 8)*176 + c2)
                    = pack2bf(ke[nf][2], ke[nf][3]);
            }
        }

        float sc[8][4] = {};
        #pragma unroll
        for (int ks = 0; ks < 4; ks++) {
            #pragma unroll
            for (int np = 0; np < 4; np++) {
                uint32_t h0, h1, h2, h3;
                uint32_t ad = sb + AT_K +
                    (uint32_t)((np*16 + (sub >> 1)*8 + lr) * 144 + (sub & 1)*16 + ks*32);
                ldsm_x4(h0, h1, h2, h3, ad);
                mma16816(sc[2*np],   qf[ks], h0, h1);
                mma16816(sc[2*np+1], qf[ks], h2, h3);
            }
        }
        __syncthreads();

        const bf16* QEp = reinterpret_cast<const bf16*>(dsm + AT_QE);
        const bf16* KEp = reinterpret_cast<const bf16*>(dsm + AT_KE);
        const float* mks = reinterpret_cast<const float*>(dsm + AT_MK);
        uint32_t ph01[8], ph23[8];
        #pragma unroll
        for (int nf = 0; nf < 8; nf++) {
            int colr = nf*8 + t*2;
            float2 mk = *reinterpret_cast<const float2*>(mks + r0 + colr);
            int rq0 = g16 * 88, rq1 = rq0 + 8*88;
            int cq = g - colr + 63;
            int rk = g16 + 15 - (colr & 15);
            float p0 = exp2f(fmaf(sc[nf][0] + __bfloat162float(QEp[rq0 + cq])
                                            + __bfloat162float(KEp[colr*88 + rk]), SC2, mk.x));
            float p1 = exp2f(fmaf(sc[nf][1] + __bfloat162float(QEp[rq0 + cq - 1])
                                            + __bfloat162float(KEp[(colr+1)*88 + rk - 1]), SC2, mk.y));
            float p2 = exp2f(fmaf(sc[nf][2] + __bfloat162float(QEp[rq1 + cq + 8])
                                            + __bfloat162float(KEp[colr*88 + rk + 8]), SC2, mk.x));
            float p3 = exp2f(fmaf(sc[nf][3] + __bfloat162float(QEp[rq1 + cq + 7])
                                            + __bfloat162float(KEp[(colr+1)*88 + rk + 7]), SC2, mk.y));
            lrow[0] += p0 + p1; lrow[1] += p2 + p3;
            ph01[nf] = pack2bf(p0, p1);
            ph23[nf] = pack2bf(p2, p3);
        }

        CP_WAIT0(); __syncthreads();

        #pragma unroll
        for (int ks = 0; ks < 4; ks++) {
            uint32_t aH[4] = {ph01[2*ks], ph23[2*ks], ph01[2*ks+1], ph23[2*ks+1]};
            #pragma unroll
            for (int np = 0; np < 4; np++) {
                uint32_t v0, v1, v2, v3;
                uint32_t ad = sb + AT_V +
                    (uint32_t)((16*ks + (sub & 1)*8 + lr) * 144 + ((sub >> 1)*8 + np*16)*2);
                ldsm_x4_t(v0, v1, v2, v3, ad);
                mma16816(acc[2*np],   aH, v0, v1);
                mma16816(acc[2*np+1], aH, v2, v3);
            }
        }
    }
    {
        #pragma unroll
        for (int o = 1; o <= 2; o <<= 1) {
            lrow[0] += __shfl_xor_sync(0xffffffffu, lrow[0], o);
            lrow[1] += __shfl_xor_sync(0xffffffffu, lrow[1], o);
        }
        float i0 = 1.f / lrow[0], i1 = 1.f / lrow[1];
        #pragma unroll
        for (int nf = 0; nf < 8; nf++) {
            save[nf][0] = acc[nf][0] * i0; save[nf][1] = acc[nf][1] * i0;
            save[nf][2] = acc[nf][2] * i1; save[nf][3] = acc[nf][3] * i1;
            acc[nf][0] = acc[nf][1] = acc[nf][2] = acc[nf][3] = 0.f;
        }
        lrow[0] = lrow[1] = 0.f;
    }

    for (int tt = 0; tt < 8; tt++) {
        const int r0 = tt * 64;
        __syncthreads();
        {
            size_t kb = (bh * SE_ + r0) * 64;
            for (int u = tid; u < 512; u += 128) {
                int r = u >> 3, c = u & 7;
                cp_async16(sb + AT_K + (uint32_t)(r * 144 + c * 16),
                           g_FK + kb + (size_t)r * 64 + c * 8);
            }
            CP_COMMIT();
            for (int u = tid; u < 512; u += 128) {
                int r = u >> 3, c = u & 7;
                cp_async16(sb + AT_V + (uint32_t)(r * 144 + c * 16),
                           g_FV + kb + (size_t)r * 64 + c * 8);
            }
            CP_COMMIT();
        }
        CP_WAIT1(); __syncthreads();

        float sc[8][4] = {};
        #pragma unroll
        for (int ks = 0; ks < 4; ks++) {
            #pragma unroll
            for (int np = 0; np < 4; np++) {
                uint32_t h0, h1, h2, h3;
                uint32_t ad = sb + AT_K +
                    (uint32_t)((np*16 + (sub >> 1)*8 + lr) * 144 + (sub & 1)*16 + ks*32);
                ldsm_x4(h0, h1, h2, h3, ad);
                mma16816(sc[2*np],   qf[ks], h0, h1);
                mma16816(sc[2*np+1], qf[ks], h2, h3);
            }
        }

        uint32_t ph01[8], ph23[8];
        #pragma unroll
        for (int nf = 0; nf < 8; nf++) {
            float p0 = exp2f(sc[nf][0] * SC2);
            float p1 = exp2f(sc[nf][1] * SC2);
            float p2 = exp2f(sc[nf][2] * SC2);
            float p3 = exp2f(sc[nf][3] * SC2);
            lrow[0] += p0 + p1; lrow[1] += p2 + p3;
            ph01[nf] = pack2bf(p0, p1);
            ph23[nf] = pack2bf(p2, p3);
        }

        CP_WAIT0(); __syncthreads();

        #pragma unroll
        for (int ks = 0; ks < 4; ks++) {
            uint32_t aH[4] = {ph01[2*ks], ph23[2*ks], ph01[2*ks+1], ph23[2*ks+1]};
            #pragma unroll
            for (int np = 0; np < 4; np++) {
                uint32_t v0, v1, v2, v3;
                uint32_t ad = sb + AT_V +
                    (uint32_t)((16*ks + (sub & 1)*8 + lr) * 144 + ((sub >> 1)*8 + np*16)*2);
                ldsm_x4_t(v0, v1, v2, v3, ad);
                mma16816(acc[2*np],   aH, v0, v1);
                mma16816(acc[2*np+1], aH, v2, v3);
            }
        }
    }

    {
        #pragma unroll
        for (int o = 1; o <= 2; o <<= 1) {
            lrow[0] += __shfl_xor_sync(0xffffffffu, lrow[0], o);
            lrow[1] += __shfl_xor_sync(0xffffffffu, lrow[1], o);
        }
        float i0 = 1.f / lrow[0], i1 = 1.f / lrow[1];
        const int rl0 = l0 + g16, rl1 = rl0 + 8;
        #pragma unroll
        for (int nf = 0; nf < 8; nf++) {
            int col = nf*8 + t*2;
            size_t b0a = (((size_t)b * S_ + rl0) * H_ + h) * 64 + col;
            size_t b1a = (((size_t)b * S_ + rl1) * H_ + h) * 64 + col;
            *reinterpret_cast<bf162*>(g_ctx + b0a) = __floats2bfloat162_rn(
                save[nf][0] + acc[nf][0]*i0, save[nf][1] + acc[nf][1]*i0);
            *reinterpret_cast<bf162*>(g_ctx + b1a) = __floats2bfloat162_rn(
                save[nf][2] + acc[nf][2]*i1, save[nf][3] + acc[nf][3]*i1);
        }
    }
}

// ---------------- LayerNorm ----------------------
__global__ void k_ln(const float* __restrict__ ga, const float* __restrict__ be,
                     float* __restrict__ out) {
    const int row = blockIdx.x;
    const int tid = threadIdx.x;
    const float* y = g_Y + (size_t)row * DM_;
    float4 tv = *reinterpret_cast<const float4*>(y + tid * 4);
    float s  = tv.x + tv.y + tv.z + tv.w;
    float s2 = tv.x * tv.x + tv.y * tv.y + tv.z * tv.z + tv.w * tv.w;
    #pragma unroll
    for (int o = 16; o > 0; o >>= 1) {
        s  += __shfl_xor_sync(0xffffffffu, s,  o);
        s2 += __shfl_xor_sync(0xffffffffu, s2, o);
    }
    __shared__ float sh[16];
    int w = tid >> 5, lane = tid & 31;
    if (lane == 0) { sh[w] = s; sh[8 + w] = s2; }
    __syncthreads();
    if (tid == 0) {
        float S = 0.f, S2 = 0.f;
        #pragma unroll
        for (int i = 0; i < 8; i++) { S += sh[i]; S2 += sh[8 + i]; }
        sh[0] = S; sh[1] = S2;
    }
    __syncthreads();
    float mu  = sh[0] * (1.f / DM_);
    float var = sh[1] * (1.f / DM_) - mu * mu;
    float r   = rsqrtf(var + 1e-12f);
    int c = tid * 4;
    float4 gv = *reinterpret_cast<const float4*>(ga + c);
    float4 bv = *reinterpret_cast<const float4*>(be + c);
    float4 o;
    o.x = (tv.x - mu) * r * gv.x + bv.x;
    o.y = (tv.y - mu) * r * gv.y + bv.y;
    o.z = (tv.z - mu) * r * gv.z + bv.z;
    o.w = (tv.w - mu) * r * gv.w + bv.w;
    *reinterpret_cast<float4*>(out + (size_t)row * DM_ + c) = o;
}

// ---------------- launch ----------------------------------------------------
extern "C" void kernel_launch(void* const* d_in, const int* in_sizes, int n_in,
                              void* d_out, int out_size) {
    (void)in_sizes; (void)n_in; (void)out_size;
    const float* hs   = (const float*)d_in[0];
    const float* mask = (const float*)d_in[1];
    const float* enc  = (const float*)d_in[2];
    const float* Wq   = (const float*)d_in[3];
    const float* bq   = (const float*)d_in[4];
    const float* Wk   = (const float*)d_in[5];
    const float* bk   = (const float*)d_in[6];
    const float* Wv   = (const float*)d_in[7];
    const float* bv   = (const float*)d_in[8];
    const float* Wfk  = (const float*)d_in[9];
    const float* bfk  = (const float*)d_in[10];
    const float* Wfv  = (const float*)d_in[11];
    const float* bfv  = (const float*)d_in[12];
    const float* E    = (const float*)d_in[13];
    const float* Wo   = (const float*)d_in[14];
    const float* bo   = (const float*)d_in[15];
    const float* lg   = (const float*)d_in[16];
    const float* lb   = (const float*)d_in[17];
    float* out = (float*)d_out;

    static bool attr_set = false;
    if (!attr_set) {
        cudaFuncSetAttribute(k_attn, cudaFuncAttributeMaxDynamicSharedMemorySize, ATTN_SMEM_BYTES);
        cudaFuncSetAttribute(k_gemm, cudaFuncAttributeMaxDynamicSharedMemorySize, GEMM_SMEM_BYTES);
        attr_set = true;
    }

    k_cvt_all<<<2592, 256>>>(hs, enc, Wq, Wk, Wv, Wo, Wfk, Wfv, E);

    k_gemm<<<dim3(8, 32, 5), 256, GEMM_SMEM_BYTES>>>(bq, bk, bv, bfk, bfv, nullptr, 0);

    k_attn<<<dim3(16, 16, 4), 128, ATTN_SMEM_BYTES>>>(mask);

    k_gemm<<<dim3(8, 32, 1), 256, GEMM_SMEM_BYTES>>>(bo, nullptr, nullptr, nullptr, nullptr, hs, 5);
    k_ln<<<4096, 256>>>(lg, lb, out);
}

// round 16
// speedup vs baseline: 1.0669x; 1.0669x over previous
#include <cuda_runtime.h>
#include <cuda_bf16.h>
#include <cstdint>

#define B_  4
#define S_  1024
#define DM_ 1024
#define H_  16
#define D_  64
#define SE_ 512
#define DF_ 512

typedef __nv_bfloat16 bf16;
typedef __nv_bfloat162 bf162;

// ===================== scratch =====================
__device__ float g_Y[B_*S_*DM_];

__device__ __align__(16) bf16 g_Q  [B_*H_*S_ *D_];
__device__ __align__(16) bf16 g_K  [B_*H_*S_ *D_];
__device__ __align__(16) bf16 g_V  [B_*H_*S_ *D_];
__device__ __align__(16) bf16 g_FK [B_*H_*SE_*D_];
__device__ __align__(16) bf16 g_FV [B_*H_*SE_*D_];
__device__ __align__(16) bf16 g_E  [2047*64];

__device__ __align__(16) bf16 g_hs  [B_*S_*DM_];
__device__ __align__(16) bf16 g_enc [B_*SE_*DF_];
__device__ __align__(16) bf16 g_ctx [B_*S_*DM_];
#define WOFF_Q  0
#define WOFF_K  1048576
#define WOFF_V  2097152
#define WOFF_O  3145728
#define WOFF_FK 4194304
#define WOFF_FV 4718592
__device__ __align__(16) bf16 g_wb[5242880];

// ===================== helpers =====================
__device__ __forceinline__ uint32_t smem_to_u32(const void* p) {
    uint32_t a;
    asm("{ .reg .u64 t; cvta.to.shared.u64 t, %1; cvt.u32.u64 %0, t; }" : "=r"(a) : "l"(p));
    return a;
}
__device__ __forceinline__ void cp_async16(uint32_t saddr, const void* gptr) {
    asm volatile("cp.async.cg.shared.global [%0], [%1], 16;" :: "r"(saddr), "l"(gptr));
}
#define CP_COMMIT() asm volatile("cp.async.commit_group;" ::: "memory")
#define CP_WAIT0()  asm volatile("cp.async.wait_group 0;" ::: "memory")
#define CP_WAIT1()  asm volatile("cp.async.wait_group 1;" ::: "memory")
#define CP_WAIT2()  asm volatile("cp.async.wait_group 2;" ::: "memory")
__device__ __forceinline__ void ldsm_x4(uint32_t& r0, uint32_t& r1, uint32_t& r2,
                                        uint32_t& r3, uint32_t addr) {
    asm volatile("ldmatrix.sync.aligned.m8n8.x4.shared.b16 {%0,%1,%2,%3}, [%4];"
                 : "=r"(r0), "=r"(r1), "=r"(r2), "=r"(r3) : "r"(addr));
}
__device__ __forceinline__ void ldsm_x4_t(uint32_t& r0, uint32_t& r1, uint32_t& r2,
                                          uint32_t& r3, uint32_t addr) {
    asm volatile("ldmatrix.sync.aligned.m8n8.x4.trans.shared.b16 {%0,%1,%2,%3}, [%4];"
                 : "=r"(r0), "=r"(r1), "=r"(r2), "=r"(r3) : "r"(addr));
}
__device__ __forceinline__ void mma16816(float* c, const uint32_t* a,
                                         uint32_t b0, uint32_t b1) {
    asm volatile(
        "mma.sync.aligned.m16n8k16.row.col.f32.bf16.bf16.f32 "
        "{%0,%1,%2,%3}, {%4,%5,%6,%7}, {%8,%9}, {%0,%1,%2,%3};"
        : "+f"(c[0]), "+f"(c[1]), "+f"(c[2]), "+f"(c[3])
        : "r"(a[0]), "r"(a[1]), "r"(a[2]), "r"(a[3]), "r"(b0), "r"(b1));
}
__device__ __forceinline__ uint32_t pack2bf(float lo, float hi) {
    bf162 v = __floats2bfloat162_rn(lo, hi);
    return *reinterpret_cast<uint32_t*>(&v);
}

// ===================== merged fp32 -> bf16 convert (4 float4 per thread) =======
__device__ __forceinline__ void cvt_one(const float* __restrict__ src, bf16* dst, int i) {
    float4 v = reinterpret_cast<const float4*>(src)[i];
    bf162* d2 = reinterpret_cast<bf162*>(dst);
    d2[2*i]   = __floats2bfloat162_rn(v.x, v.y);
    d2[2*i+1] = __floats2bfloat162_rn(v.z, v.w);
}

__global__ void __launch_bounds__(256)
k_cvt_all(const float* hs, const float* enc, const float* Wq, const float* Wk,
          const float* Wv, const float* Wo, const float* Wfk, const float* Wfv,
          const float* E) {
    int blk = blockIdx.x, tid = threadIdx.x;
    const float* src; bf16* dst; int lb, n4;
    if      (blk < 1024) { src=hs;  dst=g_hs;         lb=0;    n4=1048576; }
    else if (blk < 1280) { src=enc; dst=g_enc;        lb=1024; n4=262144; }
    else if (blk < 1536) { src=Wq;  dst=g_wb+WOFF_Q;  lb=1280; n4=262144; }
    else if (blk < 1792) { src=Wk;  dst=g_wb+WOFF_K;  lb=1536; n4=262144; }
    else if (blk < 2048) { src=Wv;  dst=g_wb+WOFF_V;  lb=1792; n4=262144; }
    else if (blk < 2304) { src=Wo;  dst=g_wb+WOFF_O;  lb=2048; n4=262144; }
    else if (blk < 2432) { src=Wfk; dst=g_wb+WOFF_FK; lb=2304; n4=131072; }
    else if (blk < 2560) { src=Wfv; dst=g_wb+WOFF_FV; lb=2432; n4=131072; }
    else                 { src=E;   dst=g_E;          lb=2560; n4=32752; }
    int i0 = (blk - lb) * 1024 + tid;
    #pragma unroll
    for (int r = 0; r < 4; r++) {
        int i = i0 + r * 256;
        if (i < n4) cvt_one(src, dst, i);
    }
}

// ===================== mma.sync bf16 GEMM (3-stage, 1 barrier/chunk) ============
#define GSTAGE 20480
#define GEMM_SMEM_BYTES (3*GSTAGE)

__global__ void __launch_bounds__(256) k_gemm(const float* __restrict__ b0p,
                                              const float* __restrict__ b1p,
                                              const float* __restrict__ b2p,
                                              const float* __restrict__ b3p,
                                              const float* __restrict__ b4p,
                                              const float* __restrict__ res,
                                              int base) {
    const int which = base + blockIdx.z;
    if (which == 3 || which == 4) { if (blockIdx.y >= 16) return; }

    extern __shared__ char dsm[];
    const uint32_t sbase = smem_to_u32(dsm);
    const int tid = threadIdx.x;
    const int lane = tid & 31, wid = tid >> 5;
    const int warp_m = wid & 1, warp_n = wid >> 1;
    const int m0 = blockIdx.y * 128, n0 = blockIdx.x * 128;
    const float* bias = blockIdx.z == 0 ? b0p : blockIdx.z == 1 ? b1p
                      : blockIdx.z == 2 ? b2p : blockIdx.z == 3 ? b3p : b4p;

    const bf16 *A, *W;
    bf16* dst = nullptr;
    int K, Sx;
    switch (which) {
        case 0: A=g_hs;  W=g_wb+WOFF_Q;  dst=g_Q;  K=1024; Sx=1024; break;
        case 1: A=g_hs;  W=g_wb+WOFF_K;  dst=g_K;  K=1024; Sx=1024; break;
        case 2: A=g_hs;  W=g_wb+WOFF_V;  dst=g_V;  K=1024; Sx=1024; break;
        case 3: A=g_enc; W=g_wb+WOFF_FK; dst=g_FK; K=512;  Sx=512;  break;
        case 4: A=g_enc; W=g_wb+WOFF_FV; dst=g_FV; K=512;  Sx=512;  break;
        default:A=g_ctx; W=g_wb+WOFF_O;  K=1024; Sx=1024; break;
    }
    const int nk = K >> 5;

    const int sub = lane >> 3, lr = lane & 7;
    const int a_row = (sub & 1) * 8 + lr, a_colB = (sub >> 1) * 16;
    const int b_row = (sub >> 1) * 8 + lr, b_colB = (sub & 1) * 16;

    float acc[4][4][4] = {};

    auto cp_chunk = [&](int c) {
        const int s = c % 3;
        const uint32_t st = sbase + s * GSTAGE;
        const int k0 = c * 32;
        #pragma unroll
        for (int i = 0; i < 2; i++) {
            int u = tid + i * 256;
            int r = u >> 2, cg = u & 3;
            uint32_t so = (uint32_t)(r * 80 + cg * 16);
            cp_async16(st + so,         A + (size_t)(m0 + r) * K + k0 + cg * 8);
            cp_async16(st + 10240 + so, W + (size_t)(n0 + r) * K + k0 + cg * 8);
        }
        CP_COMMIT();
    };

    cp_chunk(0); cp_chunk(1);
    for (int c = 0; c < nk; c++) {
        if (c + 1 < nk) { CP_WAIT1(); } else { CP_WAIT0(); }
        __syncthreads();          // chunk c visible; all warps done with c-1
        if (c + 2 < nk) cp_chunk(c + 2);   // overwrite stage (c-1)%3 — safe
        const uint32_t st = sbase + (c % 3) * GSTAGE;
        #pragma unroll
        for (int ks = 0; ks < 2; ks++) {
            uint32_t bh[8];
            #pragma unroll
            for (int np = 0; np < 2; np++) {
                uint32_t baddr = st + 10240 +
                    (uint32_t)((warp_n * 32 + np * 16 + b_row) * 80 + ks * 32 + b_colB);
                ldsm_x4(bh[np*4+0], bh[np*4+1], bh[np*4+2], bh[np*4+3], baddr);
            }
            #pragma unroll
            for (int mf = 0; mf < 4; mf++) {
                uint32_t ah[4];
                uint32_t aaddr = st +
                    (uint32_t)((warp_m * 64 + mf * 16 + a_row) * 80 + ks * 32 + a_colB);
                ldsm_x4(ah[0], ah[1], ah[2], ah[3], aaddr);
                #pragma unroll
                for (int nf = 0; nf < 4; nf++) {
                    const int np = nf >> 1, q = nf & 1;
                    mma16816(acc[mf][nf], ah, bh[np*4 + q*2], bh[np*4 + q*2 + 1]);
                }
            }
        }
    }

    const int gID = lane >> 2, tc2 = (lane & 3) * 2;
    #pragma unroll
    for (int mf = 0; mf < 4; mf++) {
        #pragma unroll
        for (int nf = 0; nf < 4; nf++) {
            int n = n0 + warp_n * 32 + nf * 8 + tc2;
            float bb0 = bias[n], bb1 = bias[n + 1];
            #pragma unroll
            for (int half = 0; half < 2; half++) {
                int m = m0 + warp_m * 64 + mf * 16 + gID + half * 8;
                float v0 = acc[mf][nf][half*2 + 0] + bb0;
                float v1 = acc[mf][nf][half*2 + 1] + bb1;
                if (which < 5) {
                    int bb = m / Sx, srow = m - bb * Sx;
                    int h = n >> 6, d = n & 63;
                    size_t o = (((size_t)(bb * H_ + h)) * Sx + srow) * 64 + d;
                    *reinterpret_cast<bf162*>(dst + o) = __floats2bfloat162_rn(v0, v1);
                } else {
                    const float2 r2 = *reinterpret_cast<const float2*>(
                        res + (size_t)m * DM_ + n);
                    float2 o = {v0 + r2.x, v1 + r2.y};
                    *reinterpret_cast<float2*>(g_Y + (size_t)m * DM_ + n) = o;
                }
            }
        }
    }
}

// ===================== tensor-core flash attention (bf16) =====================
// R11/R12/R14 kernel, unchanged (proven local optimum).
#define AT_K  0
#define AT_V  9216
#define AT_E  18432
#define AT_QE 36864
#define AT_KE 48128
#define AT_MK 59392
#define ATTN_SMEM_BYTES 63488

__global__ void __launch_bounds__(128, 3)
k_attn(const float* __restrict__ mask) {
    extern __shared__ char dsm[];
    const uint32_t sb = smem_to_u32(dsm);
    const int tid = threadIdx.x;
    const int lane = tid & 31, w = tid >> 5;
    const int g = lane >> 2, t = lane & 3;
    const int sub = lane >> 3, lr = lane & 7;
    const int l0 = blockIdx.x * 64;
    const int h  = blockIdx.y;
    const int b  = blockIdx.z;
    const size_t bh = (size_t)(b * H_ + h);
    const float SC2 = 0.125f * 1.44269504f;
    const float L2E = 1.44269504f;

    {
        float* mks = reinterpret_cast<float*>(dsm + AT_MK);
        for (int u = tid; u < 256; u += 128) {
            float4 m4 = reinterpret_cast<const float4*>(mask + b * S_)[u];
            m4.x *= L2E; m4.y *= L2E; m4.z *= L2E; m4.w *= L2E;
            reinterpret_cast<float4*>(mks)[u] = m4;
        }
    }
    {
        size_t qb = (bh * S_ + l0) * 64;
        for (int u = tid; u < 512; u += 128) {
            int r = u >> 3, c = u & 7;
            cp_async16(sb + AT_K + (uint32_t)(r * 144 + c * 16),
                       g_Q + qb + (size_t)r * 64 + c * 8);
        }
        CP_COMMIT(); CP_WAIT0();
    }
    __syncthreads();
    uint32_t qf[4][4];
    #pragma unroll
    for (int ks = 0; ks < 4; ks++) {
        uint32_t ad = sb + AT_K +
            (uint32_t)((16*w + (sub & 1)*8 + lr) * 144 + (sub >> 1)*16 + ks*32);
        ldsm_x4(qf[ks][0], qf[ks][1], qf[ks][2], qf[ks][3], ad);
    }

    float acc[8][4] = {};
    float save[8][4];
    float lrow[2] = {0.f, 0.f};
    const int g16 = 16 * w + g;

    for (int tt = 0; tt < 16; tt++) {
        const int r0 = tt * 64;
        __syncthreads();
        {
            const int jbase = l0 - r0 + 960;
            const bf16* Ep = g_E + (size_t)jbase * 64;
            for (int u = tid; u < 1016; u += 128) {
                int r = u >> 3, c = u & 7;
                cp_async16(sb + AT_E + (uint32_t)(r * 144 + c * 16),
                           Ep + (size_t)r * 64 + c * 8);
            }
            CP_COMMIT();
        }
        {
            size_t kb = (bh * S_ + r0) * 64;
            for (int u = tid; u < 512; u += 128) {
                int r = u >> 3, c = u & 7;
                cp_async16(sb + AT_K + (uint32_t)(r * 144 + c * 16),
                           g_K + kb + (size_t)r * 64 + c * 8);
            }
            CP_COMMIT();
        }
        {
            size_t kb = (bh * S_ + r0) * 64;
            for (int u = tid; u < 512; u += 128) {
                int r = u >> 3, c = u & 7;
                cp_async16(sb + AT_V + (uint32_t)(r * 144 + c * 16),
                           g_V + kb + (size_t)r * 64 + c * 8);
            }
            CP_COMMIT();
        }

        CP_WAIT2(); __syncthreads();

        {
            float qe[10][4] = {};
            #pragma unroll
            for (int ks = 0; ks < 4; ks++) {
                #pragma unroll
                for (int np = 0; np < 5; np++) {
                    uint32_t e0, e1, e2, e3;
                    uint32_t ad = sb + AT_E +
                        (uint32_t)((16*w + np*16 + (sub >> 1)*8 + lr) * 144
                                   + (sub & 1)*16 + ks*32);
                    ldsm_x4(e0, e1, e2, e3, ad);
                    mma16816(qe[2*np],   qf[ks], e0, e1);
                    mma16816(qe[2*np+1], qf[ks], e2, e3);
                }
            }
            #pragma unroll
            for (int nf = 0; nf < 10; nf++) {
                uint32_t c2 = (uint32_t)((nf*8 + t*2) * 2);
                *reinterpret_cast<uint32_t*>(dsm + AT_QE + g16*176 + c2)
                    = pack2bf(qe[nf][0], qe[nf][1]);
                *reinterpret_cast<uint32_t*>(dsm + AT_QE + (g16 + 8)*176 + c2)
                    = pack2bf(qe[nf][2], qe[nf][3]);
            }
        }

        CP_WAIT1(); __syncthreads();

        {
            float ke[10][4] = {};
            const int kb16 = 16 * (3 - w);
            #pragma unroll
            for (int ks = 0; ks < 4; ks++) {
                uint32_t ka[4];
                uint32_t aad = sb + AT_K +
                    (uint32_t)((16*w + (sub & 1)*8 + lr) * 144 + (sub >> 1)*16 + ks*32);
                ldsm_x4(ka[0], ka[1], ka[2], ka[3], aad);
                #pragma unroll
                for (int np = 0; np < 5; np++) {
                    uint32_t e0, e1, e2, e3;
                    uint32_t ad = sb + AT_E +
                        (uint32_t)((kb16 + np*16 + (sub >> 1)*8 + lr) * 144
                                   + (sub & 1)*16 + ks*32);
                    ldsm_x4(e0, e1, e2, e3, ad);
                    mma16816(ke[2*np],   ka, e0, e1);
                    mma16816(ke[2*np+1], ka, e2, e3);
                }
            }
            #pragma unroll
            for (int nf = 0; nf < 10; nf++) {
                uint32_t c2 = (uint32_t)((nf*8 + t*2) * 2);
                *reinterpret_cast<uint32_t*>(dsm + AT_KE + g16*176 + c2)
                    = pack2bf(ke[nf][0], ke[nf][1]);
                *reinterpret_cast<uint32_t*>(dsm + AT_KE + (g16 + 8)*176 + c2)
                    = pack2bf(ke[nf][2], ke[nf][3]);
            }
        }

        float sc[8][4] = {};
        #pragma unroll
        for (int ks = 0; ks < 4; ks++) {
            #pragma unroll
            for (int np = 0; np < 4; np++) {
                uint32_t h0, h1, h2, h3;
                uint32_t ad = sb + AT_K +
                    (uint32_t)((np*16 + (sub >> 1)*8 + lr) * 144 + (sub & 1)*16 + ks*32);
                ldsm_x4(h0, h1, h2, h3, ad);
                mma16816(sc[2*np],   qf[ks], h0, h1);
                mma16816(sc[2*np+1], qf[ks], h2, h3);
            }
        }
        __syncthreads();

        const bf16* QEp = reinterpret_cast<const bf16*>(dsm + AT_QE);
        const bf16* KEp = reinterpret_cast<const bf16*>(dsm + AT_KE);
        const float* mks = reinterpret_cast<const float*>(dsm + AT_MK);
        uint32_t ph01[8], ph23[8];
        #pragma unroll
        for (int nf = 0; nf < 8; nf++) {
            int colr = nf*8 + t*2;
            float2 mk = *reinterpret_cast<const float2*>(mks + r0 + colr);
            int rq0 = g16 * 88, rq1 = rq0 + 8*88;
            int cq = g - colr + 63;
            int rk = g16 + 15 - (colr & 15);
            float p0 = exp2f(fmaf(sc[nf][0] + __bfloat162float(QEp[rq0 + cq])
                                            + __bfloat162float(KEp[colr*88 + rk]), SC2, mk.x));
            float p1 = exp2f(fmaf(sc[nf][1] + __bfloat162float(QEp[rq0 + cq - 1])
                                            + __bfloat162float(KEp[(colr+1)*88 + rk - 1]), SC2, mk.y));
            float p2 = exp2f(fmaf(sc[nf][2] + __bfloat162float(QEp[rq1 + cq + 8])
                                            + __bfloat162float(KEp[colr*88 + rk + 8]), SC2, mk.x));
            float p3 = exp2f(fmaf(sc[nf][3] + __bfloat162float(QEp[rq1 + cq + 7])
                                            + __bfloat162float(KEp[(colr+1)*88 + rk + 7]), SC2, mk.y));
            lrow[0] += p0 + p1; lrow[1] += p2 + p3;
            ph01[nf] = pack2bf(p0, p1);
            ph23[nf] = pack2bf(p2, p3);
        }

        CP_WAIT0(); __syncthreads();

        #pragma unroll
        for (int ks = 0; ks < 4; ks++) {
            uint32_t aH[4] = {ph01[2*ks], ph23[2*ks], ph01[2*ks+1], ph23[2*ks+1]};
            #pragma unroll
            for (int np = 0; np < 4; np++) {
                uint32_t v0, v1, v2, v3;
                uint32_t ad = sb + AT_V +
                    (uint32_t)((16*ks + (sub & 1)*8 + lr) * 144 + ((sub >> 1)*8 + np*16)*2);
                ldsm_x4_t(v0, v1, v2, v3, ad);
                mma16816(acc[2*np],   aH, v0, v1);
                mma16816(acc[2*np+1], aH, v2, v3);
            }
        }
    }
    {
        #pragma unroll
        for (int o = 1; o <= 2; o <<= 1) {
            lrow[0] += __shfl_xor_sync(0xffffffffu, lrow[0], o);
            lrow[1] += __shfl_xor_sync(0xffffffffu, lrow[1], o);
        }
        float i0 = 1.f / lrow[0], i1 = 1.f / lrow[1];
        #pragma unroll
        for (int nf = 0; nf < 8; nf++) {
            save[nf][0] = acc[nf][0] * i0; save[nf][1] = acc[nf][1] * i0;
            save[nf][2] = acc[nf][2] * i1; save[nf][3] = acc[nf][3] * i1;
            acc[nf][0] = acc[nf][1] = acc[nf][2] = acc[nf][3] = 0.f;
        }
        lrow[0] = lrow[1] = 0.f;
    }

    for (int tt = 0; tt < 8; tt++) {
        const int r0 = tt * 64;
        __syncthreads();
        {
            size_t kb = (bh * SE_ + r0) * 64;
            for (int u = tid; u < 512; u += 128) {
                int r = u >> 3, c = u & 7;
                cp_async16(sb + AT_K + (uint32_t)(r * 144 + c * 16),
                           g_FK + kb + (size_t)r * 64 + c * 8);
            }
            CP_COMMIT();
            for (int u = tid; u < 512; u += 128) {
                int r = u >> 3, c = u & 7;
                cp_async16(sb + AT_V + (uint32_t)(r * 144 + c * 16),
                           g_FV + kb + (size_t)r * 64 + c * 8);
            }
            CP_COMMIT();
        }
        CP_WAIT1(); __syncthreads();

        float sc[8][4] = {};
        #pragma unroll
        for (int ks = 0; ks < 4; ks++) {
            #pragma unroll
            for (int np = 0; np < 4; np++) {
                uint32_t h0, h1, h2, h3;
                uint32_t ad = sb + AT_K +
                    (uint32_t)((np*16 + (sub >> 1)*8 + lr) * 144 + (sub & 1)*16 + ks*32);
                ldsm_x4(h0, h1, h2, h3, ad);
                mma16816(sc[2*np],   qf[ks], h0, h1);
                mma16816(sc[2*np+1], qf[ks], h2, h3);
            }
        }

        uint32_t ph01[8], ph23[8];
        #pragma unroll
        for (int nf = 0; nf < 8; nf++) {
            float p0 = exp2f(sc[nf][0] * SC2);
            float p1 = exp2f(sc[nf][1] * SC2);
            float p2 = exp2f(sc[nf][2] * SC2);
            float p3 = exp2f(sc[nf][3] * SC2);
            lrow[0] += p0 + p1; lrow[1] += p2 + p3;
            ph01[nf] = pack2bf(p0, p1);
            ph23[nf] = pack2bf(p2, p3);
        }

        CP_WAIT0(); __syncthreads();

        #pragma unroll
        for (int ks = 0; ks < 4; ks++) {
            uint32_t aH[4] = {ph01[2*ks], ph23[2*ks], ph01[2*ks+1], ph23[2*ks+1]};
            #pragma unroll
            for (int np = 0; np < 4; np++) {
                uint32_t v0, v1, v2, v3;
                uint32_t ad = sb + AT_V +
                    (uint32_t)((16*ks + (sub & 1)*8 + lr) * 144 + ((sub >> 1)*8 + np*16)*2);
                ldsm_x4_t(v0, v1, v2, v3, ad);
                mma16816(acc[2*np],   aH, v0, v1);
                mma16816(acc[2*np+1], aH, v2, v3);
            }
        }
    }

    {
        #pragma unroll
        for (int o = 1; o <= 2; o <<= 1) {
            lrow[0] += __shfl_xor_sync(0xffffffffu, lrow[0], o);
            lrow[1] += __shfl_xor_sync(0xffffffffu, lrow[1], o);
        }
        float i0 = 1.f / lrow[0], i1 = 1.f / lrow[1];
        const int rl0 = l0 + g16, rl1 = rl0 + 8;
        #pragma unroll
        for (int nf = 0; nf < 8; nf++) {
            int col = nf*8 + t*2;
            size_t b0a = (((size_t)b * S_ + rl0) * H_ + h) * 64 + col;
            size_t b1a = (((size_t)b * S_ + rl1) * H_ + h) * 64 + col;
            *reinterpret_cast<bf162*>(g_ctx + b0a) = __floats2bfloat162_rn(
                save[nf][0] + acc[nf][0]*i0, save[nf][1] + acc[nf][1]*i0);
            *reinterpret_cast<bf162*>(g_ctx + b1a) = __floats2bfloat162_rn(
                save[nf][2] + acc[nf][2]*i1, save[nf][3] + acc[nf][3]*i1);
        }
    }
}

// ---------------- LayerNorm ----------------------
__global__ void k_ln(const float* __restrict__ ga, const float* __restrict__ be,
                     float* __restrict__ out) {
    const int row = blockIdx.x;
    const int tid = threadIdx.x;
    const float* y = g_Y + (size_t)row * DM_;
    float4 tv = *reinterpret_cast<const float4*>(y + tid * 4);
    float s  = tv.x + tv.y + tv.z + tv.w;
    float s2 = tv.x * tv.x + tv.y * tv.y + tv.z * tv.z + tv.w * tv.w;
    #pragma unroll
    for (int o = 16; o > 0; o >>= 1) {
        s  += __shfl_xor_sync(0xffffffffu, s,  o);
        s2 += __shfl_xor_sync(0xffffffffu, s2, o);
    }
    __shared__ float sh[16];
    int w = tid >> 5, lane = tid & 31;
    if (lane == 0) { sh[w] = s; sh[8 + w] = s2; }
    __syncthreads();
    if (tid == 0) {
        float S = 0.f, S2 = 0.f;
        #pragma unroll
        for (int i = 0; i < 8; i++) { S += sh[i]; S2 += sh[8 + i]; }
        sh[0] = S; sh[1] = S2;
    }
    __syncthreads();
    float mu  = sh[0] * (1.f / DM_);
    float var = sh[1] * (1.f / DM_) - mu * mu;
    float r   = rsqrtf(var + 1e-12f);
    int c = tid * 4;
    float4 gv = *reinterpret_cast<const float4*>(ga + c);
    float4 bv = *reinterpret_cast<const float4*>(be + c);
    float4 o;
    o.x = (tv.x - mu) * r * gv.x + bv.x;
    o.y = (tv.y - mu) * r * gv.y + bv.y;
    o.z = (tv.z - mu) * r * gv.z + bv.z;
    o.w = (tv.w - mu) * r * gv.w + bv.w;
    *reinterpret_cast<float4*>(out + (size_t)row * DM_ + c) = o;
}

// ---------------- launch ----------------------------------------------------
extern "C" void kernel_launch(void* const* d_in, const int* in_sizes, int n_in,
                              void* d_out, int out_size) {
    (void)in_sizes; (void)n_in; (void)out_size;
    const float* hs   = (const float*)d_in[0];
    const float* mask = (const float*)d_in[1];
    const float* enc  = (const float*)d_in[2];
    const float* Wq   = (const float*)d_in[3];
    const float* bq   = (const float*)d_in[4];
    const float* Wk   = (const float*)d_in[5];
    const float* bk   = (const float*)d_in[6];
    const float* Wv   = (const float*)d_in[7];
    const float* bv   = (const float*)d_in[8];
    const float* Wfk  = (const float*)d_in[9];
    const float* bfk  = (const float*)d_in[10];
    const float* Wfv  = (const float*)d_in[11];
    const float* bfv  = (const float*)d_in[12];
    const float* E    = (const float*)d_in[13];
    const float* Wo   = (const float*)d_in[14];
    const float* bo   = (const float*)d_in[15];
    const float* lg   = (const float*)d_in[16];
    const float* lb   = (const float*)d_in[17];
    float* out = (float*)d_out;

    static bool attr_set = false;
    if (!attr_set) {
        cudaFuncSetAttribute(k_attn, cudaFuncAttributeMaxDynamicSharedMemorySize, ATTN_SMEM_BYTES);
        cudaFuncSetAttribute(k_gemm, cudaFuncAttributeMaxDynamicSharedMemorySize, GEMM_SMEM_BYTES);
        attr_set = true;
    }

    k_cvt_all<<<2592, 256>>>(hs, enc, Wq, Wk, Wv, Wo, Wfk, Wfv, E);

    k_gemm<<<dim3(8, 32, 5), 256, GEMM_SMEM_BYTES>>>(bq, bk, bv, bfk, bfv, nullptr, 0);

    k_attn<<<dim3(16, 16, 4), 128, ATTN_SMEM_BYTES>>>(mask);

    k_gemm<<<dim3(8, 32, 1), 256, GEMM_SMEM_BYTES>>>(bo, nullptr, nullptr, nullptr, nullptr, hs, 5);
    k_ln<<<4096, 256>>>(lg, lb, out);
}